// round 1
// baseline (speedup 1.0000x reference)
#include <cuda_runtime.h>
#include <math.h>

#define B_   2
#define T_   4096
#define D_   512
#define H_   8
#define HD_  64
#define W_   32
#define HID_ 1536
#define NTOK (B_*T_)

// ---------------- scratch (device globals; no allocs allowed) ----------------
__device__ float g_h  [(size_t)NTOK * D_];
__device__ float g_q  [(size_t)NTOK * D_];
__device__ float g_kv [(size_t)NTOK * 2 * D_];
__device__ float g_msg[(size_t)NTOK * D_];
__device__ float g_tmp[(size_t)NTOK * D_];
__device__ float g_y  [(size_t)NTOK * D_];
__device__ float g_gate[(size_t)NTOK * HID_];
__device__ float g_val [(size_t)NTOK * HID_];
__device__ float g_z  [(size_t)NTOK * D_];

// ---------------- GEMM: C[M,N] = A[M,K] @ B[K,N] ----------------
// BM=128, BN=64, BK=16, 256 threads, 8x4 per-thread micro-tile.
__global__ __launch_bounds__(256) void gemm_kernel(
    const float* __restrict__ A, const float* __restrict__ Bm,
    float* __restrict__ C, int N, int K) {
  __shared__ float As[16][128];
  __shared__ float Bs[16][64];
  const int tid = threadIdx.x;
  const int bm = blockIdx.y * 128;
  const int bn = blockIdx.x * 64;
  const int ty = tid >> 4;         // 0..15 -> rows ty*8..+7
  const int tx = tid & 15;         // 0..15 -> cols tx*4..+3

  float acc[8][4] = {};

  const int arow = tid >> 1;             // 0..127
  const int akc  = (tid & 1) * 8;        // 0 or 8
  const int bkr  = tid >> 4;             // 0..15
  const int bnc  = (tid & 15) << 2;      // 0..60
  const float* Ap = A + (size_t)(bm + arow) * K + akc;
  const float* Bp = Bm + (size_t)bkr * N + bn + bnc;

  for (int k0 = 0; k0 < K; k0 += 16) {
    float4 a0 = *(const float4*)(Ap + k0);
    float4 a1 = *(const float4*)(Ap + k0 + 4);
    float4 bv = *(const float4*)(Bp + (size_t)k0 * N);
    As[akc+0][arow]=a0.x; As[akc+1][arow]=a0.y; As[akc+2][arow]=a0.z; As[akc+3][arow]=a0.w;
    As[akc+4][arow]=a1.x; As[akc+5][arow]=a1.y; As[akc+6][arow]=a1.z; As[akc+7][arow]=a1.w;
    *(float4*)&Bs[bkr][bnc] = bv;
    __syncthreads();
#pragma unroll
    for (int k = 0; k < 16; k++) {
      float4 x0 = *(const float4*)&As[k][ty*8];
      float4 x1 = *(const float4*)&As[k][ty*8+4];
      float4 yv = *(const float4*)&Bs[k][tx*4];
      float ar[8] = {x0.x,x0.y,x0.z,x0.w,x1.x,x1.y,x1.z,x1.w};
      float br[4] = {yv.x,yv.y,yv.z,yv.w};
#pragma unroll
      for (int i = 0; i < 8; i++)
#pragma unroll
        for (int j = 0; j < 4; j++) acc[i][j] += ar[i]*br[j];
    }
    __syncthreads();
  }
#pragma unroll
  for (int i = 0; i < 8; i++) {
    float4 o = make_float4(acc[i][0],acc[i][1],acc[i][2],acc[i][3]);
    *(float4*)&C[(size_t)(bm + ty*8 + i) * N + bn + tx*4] = o;
  }
}

// ---------------- windowed sigmoid attention ----------------
// One block = (token chunk of 128, head, batch). k/v staged transposed in SMEM
// ([d][tok], pad 161 -> conflict-free lane-per-token reads). q & acc in regs.
#define AT_TOKS (128 + W_)   /* 160 */
#define AT_PAD  161

__global__ __launch_bounds__(128) void attn_kernel(
    const float* __restrict__ q, const float* __restrict__ kv,
    float* __restrict__ msg) {
  extern __shared__ float sm[];
  float* ks = sm;                    // [64][AT_PAD]
  float* vs = sm + 64 * AT_PAD;      // [64][AT_PAD]
  const int c = blockIdx.x, h = blockIdx.y, b = blockIdx.z;
  const int base = c * 128 - W_;     // global token of smem slot 0
  const int tid = threadIdx.x;

  // fill k/v tiles (zero for tokens before batch start)
  for (int i4 = tid; i4 < AT_TOKS * 32; i4 += 128) {
    int tok = i4 >> 5;
    int dq  = (i4 & 31) << 2;        // 0..124, step 4
    int tg  = base + tok;
    float4 v = make_float4(0.f, 0.f, 0.f, 0.f);
    if (tg >= 0)
      v = *(const float4*)&kv[((size_t)(b*T_ + tg)*H_ + h)*128 + dq];
    float* dst = (dq < 64) ? (ks + dq*AT_PAD + tok) : (vs + (dq-64)*AT_PAD + tok);
    dst[0]        = v.x;
    dst[AT_PAD]   = v.y;
    dst[2*AT_PAD] = v.z;
    dst[3*AT_PAD] = v.w;
  }
  __syncthreads();

  const int tg = c * 128 + tid;      // this thread's token
  const float* qp = &q[((size_t)(b*T_ + tg)*H_ + h)*HD_];
  float qr[64];
#pragma unroll
  for (int i = 0; i < 16; i++) {
    float4 f = *(const float4*)(qp + 4*i);
    qr[4*i]=f.x; qr[4*i+1]=f.y; qr[4*i+2]=f.z; qr[4*i+3]=f.w;
  }
  float acc[64];
#pragma unroll
  for (int d = 0; d < 64; d++) acc[d] = 0.f;

  const int jt = tid + W_;           // smem index of token tg
  for (int w = 0; w < W_; w++) {
    int j = jt - 1 - w;              // window: previous 32 tokens
    float s = 0.f;
#pragma unroll
    for (int d = 0; d < 64; d++) s += qr[d] * ks[d*AT_PAD + j];
    float tau = 1.f / (1.f + expf(-s * 0.125f));   // / sqrt(64)
#pragma unroll
    for (int d = 0; d < 64; d++) acc[d] += tau * vs[d*AT_PAD + j];
  }
  float* mp = &msg[((size_t)(b*T_ + tg)*H_ + h)*HD_];
#pragma unroll
  for (int i = 0; i < 16; i++)
    *(float4*)(mp + 4*i) = make_float4(acc[4*i],acc[4*i+1],acc[4*i+2],acc[4*i+3]);
}

// ---------------- LayerNorm (+residual, +sin modulation) ----------------
// MODE 0: out = LN(x)
// MODE 1: out = LN(x+add) * (1 + amp*sin(t*freqs + phases))
// MODE 2: out = LN(x+add)
template<int MODE>
__global__ __launch_bounds__(128) void ln_kernel(
    const float* __restrict__ x, const float* __restrict__ add,
    const float* __restrict__ g, const float* __restrict__ bb,
    const float* __restrict__ freqs, const float* __restrict__ phases,
    const float* __restrict__ amp, float* __restrict__ out) {
  const int row = blockIdx.x;
  const int i = threadIdx.x;        // 128 threads * float4 = 512
  float4 f = ((const float4*)(x + (size_t)row*D_))[i];
  if (MODE >= 1) {
    float4 a = ((const float4*)(add + (size_t)row*D_))[i];
    f.x+=a.x; f.y+=a.y; f.z+=a.z; f.w+=a.w;
  }
  float s  = f.x + f.y + f.z + f.w;
  float ss = f.x*f.x + f.y*f.y + f.z*f.z + f.w*f.w;
#pragma unroll
  for (int o = 16; o > 0; o >>= 1) {
    s  += __shfl_xor_sync(0xffffffffu, s,  o);
    ss += __shfl_xor_sync(0xffffffffu, ss, o);
  }
  __shared__ float rs[4], rss[4];
  if ((i & 31) == 0) { rs[i>>5] = s; rss[i>>5] = ss; }
  __syncthreads();
  s  = rs[0]  + rs[1]  + rs[2]  + rs[3];
  ss = rss[0] + rss[1] + rss[2] + rss[3];
  const float mu   = s * (1.f/D_);
  const float var  = ss * (1.f/D_) - mu*mu;
  const float rstd = rsqrtf(var + 1e-5f);
  float4 gv = ((const float4*)g)[i];
  float4 bv = ((const float4*)bb)[i];
  float4 o;
  o.x = (f.x-mu)*rstd*gv.x + bv.x;
  o.y = (f.y-mu)*rstd*gv.y + bv.y;
  o.z = (f.z-mu)*rstd*gv.z + bv.z;
  o.w = (f.w-mu)*rstd*gv.w + bv.w;
  if (MODE == 1) {
    float t  = (float)(row & (T_-1));
    float av = amp[0];
    float4 fr = ((const float4*)freqs)[i];
    float4 ph = ((const float4*)phases)[i];
    o.x *= 1.f + av*sinf(t*fr.x + ph.x);
    o.y *= 1.f + av*sinf(t*fr.y + ph.y);
    o.z *= 1.f + av*sinf(t*fr.z + ph.z);
    o.w *= 1.f + av*sinf(t*fr.w + ph.w);
  }
  ((float4*)(out + (size_t)row*D_))[i] = o;
}

// ---------------- silu(gate) * val ----------------
__global__ void silu_mul_kernel(const float* __restrict__ gg,
                                const float* __restrict__ vv,
                                float* __restrict__ out, int n4) {
  int i = blockIdx.x*blockDim.x + threadIdx.x;
  if (i >= n4) return;
  float4 gq = ((const float4*)gg)[i];
  float4 vq = ((const float4*)vv)[i];
  float4 o;
  o.x = gq.x / (1.f + expf(-gq.x)) * vq.x;
  o.y = gq.y / (1.f + expf(-gq.y)) * vq.y;
  o.z = gq.z / (1.f + expf(-gq.z)) * vq.z;
  o.w = gq.w / (1.f + expf(-gq.w)) * vq.w;
  ((float4*)out)[i] = o;
}

// ---------------- launch ----------------
extern "C" void kernel_launch(void* const* d_in, const int* in_sizes, int n_in,
                              void* d_out, int out_size) {
  const float* x      = (const float*)d_in[0];
  const float* pre_g  = (const float*)d_in[1];
  const float* pre_b  = (const float*)d_in[2];
  const float* wq     = (const float*)d_in[3];
  const float* wkv    = (const float*)d_in[4];
  const float* wo     = (const float*)d_in[5];
  const float* attn_g = (const float*)d_in[6];
  const float* attn_b = (const float*)d_in[7];
  const float* freqs  = (const float*)d_in[8];
  const float* phases = (const float*)d_in[9];
  const float* amp    = (const float*)d_in[10];
  const float* w_gate = (const float*)d_in[11];
  const float* w_val  = (const float*)d_in[12];
  const float* w_proj = (const float*)d_in[13];
  const float* ffn_g  = (const float*)d_in[14];
  const float* ffn_b  = (const float*)d_in[15];

  float *h, *q, *kv, *msg, *tmp, *y, *gate, *val, *z;
  cudaGetSymbolAddress((void**)&h,    g_h);
  cudaGetSymbolAddress((void**)&q,    g_q);
  cudaGetSymbolAddress((void**)&kv,   g_kv);
  cudaGetSymbolAddress((void**)&msg,  g_msg);
  cudaGetSymbolAddress((void**)&tmp,  g_tmp);
  cudaGetSymbolAddress((void**)&y,    g_y);
  cudaGetSymbolAddress((void**)&gate, g_gate);
  cudaGetSymbolAddress((void**)&val,  g_val);
  cudaGetSymbolAddress((void**)&z,    g_z);

  const int ATTN_SMEM = 2 * 64 * AT_PAD * sizeof(float);   // 82432 B
  cudaFuncSetAttribute(attn_kernel, cudaFuncAttributeMaxDynamicSharedMemorySize, ATTN_SMEM);

  // 1) h = LN(x)
  ln_kernel<0><<<NTOK, 128>>>(x, nullptr, pre_g, pre_b, nullptr, nullptr, nullptr, h);
  // 2) q = h @ wq ; kv = h @ wkv
  gemm_kernel<<<dim3(D_/64,  NTOK/128), 256>>>(h, wq,  q,  D_,     D_);
  gemm_kernel<<<dim3(2*D_/64,NTOK/128), 256>>>(h, wkv, kv, 2*D_,   D_);
  // 3) windowed sigmoid attention -> msg
  attn_kernel<<<dim3(T_/128, H_, B_), 128, ATTN_SMEM>>>(q, kv, msg);
  // 4) tmp = msg @ wo ; y = LN(h+tmp) * (1 + amp*sin(t*freqs+phases))
  gemm_kernel<<<dim3(D_/64, NTOK/128), 256>>>(msg, wo, tmp, D_, D_);
  ln_kernel<1><<<NTOK, 128>>>(h, tmp, attn_g, attn_b, freqs, phases, amp, y);
  // 5) FFN
  gemm_kernel<<<dim3(HID_/64, NTOK/128), 256>>>(y, w_gate, gate, HID_, D_);
  gemm_kernel<<<dim3(HID_/64, NTOK/128), 256>>>(y, w_val,  val,  HID_, D_);
  {
    int n4 = NTOK * HID_ / 4;
    silu_mul_kernel<<<(n4 + 255)/256, 256>>>(gate, val, gate, n4);
  }
  gemm_kernel<<<dim3(D_/64, NTOK/128), 256>>>(gate, w_proj, z, D_, HID_);
  // 6) out = LN(y + z)
  ln_kernel<2><<<NTOK, 128>>>(y, z, ffn_g, ffn_b, nullptr, nullptr, nullptr, (float*)d_out);
}

// round 3
// speedup vs baseline: 2.4239x; 2.4239x over previous
#include <cuda_runtime.h>
#include <cuda_bf16.h>
#include <math.h>
#include <stdint.h>

#define B_   2
#define T_   4096
#define D_   512
#define H_   8
#define HD_  64
#define W_   32
#define HID_ 1536
#define NTOK (B_*T_)

// ---------------- scratch (device globals; no allocs allowed) ----------------
__device__ float g_h  [(size_t)NTOK * D_];
__device__ float g_q  [(size_t)NTOK * D_];
__device__ float g_kv [(size_t)NTOK * 2 * D_];
__device__ float g_msg[(size_t)NTOK * D_];
__device__ float g_tmp[(size_t)NTOK * D_];
__device__ float g_y  [(size_t)NTOK * D_];
__device__ float g_gate[(size_t)NTOK * HID_];
__device__ float g_val [(size_t)NTOK * HID_];
__device__ float g_z  [(size_t)NTOK * D_];
// bf16 split buffers: A2 up to [8192, 3*1536], B2 up to [1536, 3*512] / [512, 3*1536]
__device__ __nv_bfloat16 g_a2[(size_t)NTOK * 3 * HID_];
__device__ __nv_bfloat16 g_b2[(size_t)2359296];

// ======================= PTX helpers (baseline ISA only) =======================
__device__ __forceinline__ uint32_t s2u(const void* p) {
  uint32_t a;
  asm("{ .reg .u64 t; cvta.to.shared.u64 t, %1; cvt.u32.u64 %0, t; }" : "=r"(a) : "l"(p));
  return a;
}
__device__ __forceinline__ void cp16(uint32_t dst, const void* src) {
  asm volatile("cp.async.cg.shared.global [%0], [%1], 16;" :: "r"(dst), "l"(src) : "memory");
}
__device__ __forceinline__ void cp_commit() { asm volatile("cp.async.commit_group;" ::: "memory"); }
template<int N>
__device__ __forceinline__ void cp_wait() { asm volatile("cp.async.wait_group %0;" :: "n"(N) : "memory"); }

__device__ __forceinline__ void ldsm4(uint32_t* r, uint32_t addr) {
  asm volatile("ldmatrix.sync.aligned.m8n8.x4.shared.b16 {%0,%1,%2,%3}, [%4];"
               : "=r"(r[0]), "=r"(r[1]), "=r"(r[2]), "=r"(r[3]) : "r"(addr));
}
__device__ __forceinline__ void mma16816(float* d, const uint32_t* a, const uint32_t* b) {
  asm volatile(
      "mma.sync.aligned.m16n8k16.row.col.f32.bf16.bf16.f32 "
      "{%0,%1,%2,%3}, {%4,%5,%6,%7}, {%8,%9}, {%0,%1,%2,%3};"
      : "+f"(d[0]), "+f"(d[1]), "+f"(d[2]), "+f"(d[3])
      : "r"(a[0]), "r"(a[1]), "r"(a[2]), "r"(a[3]), "r"(b[0]), "r"(b[1]));
}

// ======================= split kernels (fp32 -> hi/lo bf16) =======================
// A2[m, 3K] = [hi | lo | hi]
__global__ __launch_bounds__(256) void split_a_kernel(
    const float* __restrict__ in, __nv_bfloat16* __restrict__ out, int K) {
  int idx = blockIdx.x * 256 + threadIdx.x;      // over M*K/4
  int kq = K >> 2;
  int m = idx / kq;
  int k = (idx - m * kq) << 2;
  float4 v = *(const float4*)(in + (size_t)m * K + k);
  __nv_bfloat16 h0 = __float2bfloat16(v.x), h1 = __float2bfloat16(v.y);
  __nv_bfloat16 h2 = __float2bfloat16(v.z), h3 = __float2bfloat16(v.w);
  __nv_bfloat16 l0 = __float2bfloat16(v.x - __bfloat162float(h0));
  __nv_bfloat16 l1 = __float2bfloat16(v.y - __bfloat162float(h1));
  __nv_bfloat16 l2 = __float2bfloat16(v.z - __bfloat162float(h2));
  __nv_bfloat16 l3 = __float2bfloat16(v.w - __bfloat162float(h3));
  union { __nv_bfloat16 b[4]; uint2 u; } H, L;
  H.b[0]=h0; H.b[1]=h1; H.b[2]=h2; H.b[3]=h3;
  L.b[0]=l0; L.b[1]=l1; L.b[2]=l2; L.b[3]=l3;
  size_t base = (size_t)m * 3 * K;
  *(uint2*)(out + base + k)         = H.u;
  *(uint2*)(out + base + K + k)     = L.u;
  *(uint2*)(out + base + 2 * K + k) = H.u;
}

// w[K,N] -> B2[n, 3K] = [hi | hi | lo]
__global__ void split_bt_kernel(const float* __restrict__ w,
                                __nv_bfloat16* __restrict__ out, int K, int N) {
  __shared__ float t[32][33];
  int n0 = blockIdx.x * 32, k0 = blockIdx.y * 32;
  t[threadIdx.y][threadIdx.x] = w[(size_t)(k0 + threadIdx.y) * N + n0 + threadIdx.x];
  __syncthreads();
  int n = n0 + threadIdx.y, k = k0 + threadIdx.x;
  float x = t[threadIdx.x][threadIdx.y];
  __nv_bfloat16 hi = __float2bfloat16(x);
  __nv_bfloat16 lo = __float2bfloat16(x - __bfloat162float(hi));
  size_t base = (size_t)n * 3 * K;
  out[base + k]         = hi;
  out[base + K + k]     = hi;
  out[base + 2 * K + k] = lo;
}

// ======================= mma.sync bf16 GEMM =======================
// C[M,N] = A2[M,K3] @ B2[N,K3]^T, bf16 in / fp32 out.
// CTA tile 128x128, BK=64 (128B rows, xor swizzle), 3-stage cp.async pipeline.
// 8 warps, warp tile 32m x 64n (2 x 8 mma tiles of m16n8k16).
#define STAGE_BYTES 32768          /* A 16KB + B 16KB */
#define GEMM_DYN_SMEM (3*STAGE_BYTES + 1024)

__global__ __launch_bounds__(256, 2) void gemm_mma(
    const __nv_bfloat16* __restrict__ A2, const __nv_bfloat16* __restrict__ B2,
    float* __restrict__ C, int N, int K3) {
  extern __shared__ char smraw[];
  uint32_t sb0 = s2u(smraw);
  const uint32_t sb = sb0 + ((1024u - (sb0 & 1023u)) & 1023u);

  const int tid = threadIdx.x, lane = tid & 31, wid = tid >> 5;
  const int bm = blockIdx.y * 128, bn = blockIdx.x * 128;
  const int wm = (wid >> 1) * 32, wn = (wid & 1) * 64;

  // cp.async slots: per stage, A = 1024 chunks of 16B, B = 1024; 4+4 per thread
  uint32_t aOff[4], bOff[4];
  const char *aSrc[4], *bSrc[4];
#pragma unroll
  for (int j = 0; j < 4; j++) {
    int s = tid + j * 256, r = s >> 3, c = s & 7;
    uint32_t off = (uint32_t)(r * 128 + ((c ^ (r & 7)) << 4));
    aOff[j] = off;             aBrk: ;
    bOff[j] = off;
    aSrc[j] = (const char*)(A2 + (size_t)(bm + r) * K3) + c * 16;
    bSrc[j] = (const char*)(B2 + (size_t)(bn + r) * K3) + c * 16;
  }

  float acc[2][8][4];
#pragma unroll
  for (int mt = 0; mt < 2; mt++)
#pragma unroll
    for (int nt = 0; nt < 8; nt++)
#pragma unroll
      for (int e = 0; e < 4; e++) acc[mt][nt][e] = 0.f;

  // ldmatrix lane geometry
  const int arow = wm + (lane & 15);                       // + mt*16
  const int ach  = lane >> 4;                              // + 2*ks
  const int brow = wn + (lane & 7) + ((lane >> 1) & 8);    // + nt*16
  const int bch  = (lane >> 3) & 1;                        // + 2*ks

  const int nIter = K3 >> 6;

  // stage loader
  auto loadStage = [&](int i) {
    uint32_t st = sb + (uint32_t)(i % 3) * STAGE_BYTES;
    size_t koff = (size_t)i * 128;      // 64 bf16 = 128 B
#pragma unroll
    for (int j = 0; j < 4; j++) cp16(st + aOff[j], aSrc[j] + koff);
#pragma unroll
    for (int j = 0; j < 4; j++) cp16(st + 16384 + bOff[j], bSrc[j] + koff);
    cp_commit();
  };

  loadStage(0);
  loadStage(1);

  for (int i = 0; i < nIter; i++) {
    if (i + 2 < nIter) { loadStage(i + 2); cp_wait<2>(); }
    else if (i + 1 < nIter) cp_wait<1>();
    else cp_wait<0>();
    __syncthreads();

    const uint32_t sa  = sb + (uint32_t)(i % 3) * STAGE_BYTES;
    const uint32_t sbB = sa + 16384;
#pragma unroll
    for (int ks = 0; ks < 4; ks++) {
      uint32_t afr[2][4];
#pragma unroll
      for (int mt = 0; mt < 2; mt++) {
        int row = arow + mt * 16;
        int ch  = 2 * ks + ach;
        ldsm4(afr[mt], sa + row * 128 + (((uint32_t)(ch ^ (row & 7))) << 4));
      }
      uint32_t bfr[4][4];
#pragma unroll
      for (int nt = 0; nt < 4; nt++) {
        int row = brow + nt * 16;
        int ch  = 2 * ks + bch;
        ldsm4(bfr[nt], sbB + row * 128 + (((uint32_t)(ch ^ (row & 7))) << 4));
      }
#pragma unroll
      for (int mt = 0; mt < 2; mt++)
#pragma unroll
        for (int n8 = 0; n8 < 8; n8++)
          mma16816(acc[mt][n8], afr[mt], &bfr[n8 >> 1][(n8 & 1) * 2]);
    }
    __syncthreads();
  }

  // epilogue: direct register -> gmem (float2 pairs)
  const int crow = lane >> 2;
  const int ccol = (lane & 3) * 2;
#pragma unroll
  for (int mt = 0; mt < 2; mt++) {
#pragma unroll
    for (int n8 = 0; n8 < 8; n8++) {
      size_t r0 = (size_t)(bm + wm + mt * 16 + crow) * N + (bn + wn + n8 * 8 + ccol);
      *(float2*)&C[r0]              = make_float2(acc[mt][n8][0], acc[mt][n8][1]);
      *(float2*)&C[r0 + (size_t)8 * N] = make_float2(acc[mt][n8][2], acc[mt][n8][3]);
    }
  }
}

// ======================= windowed sigmoid attention =======================
#define AT_TOKS (128 + W_)
#define AT_PAD  161

__global__ __launch_bounds__(128) void attn_kernel(
    const float* __restrict__ q, const float* __restrict__ kv,
    float* __restrict__ msg) {
  extern __shared__ float smf[];
  float* ks = smf;
  float* vs = smf + 64 * AT_PAD;
  const int c = blockIdx.x, h = blockIdx.y, b = blockIdx.z;
  const int base = c * 128 - W_;
  const int tid = threadIdx.x;

  for (int i4 = tid; i4 < AT_TOKS * 32; i4 += 128) {
    int tok = i4 >> 5;
    int dq  = (i4 & 31) << 2;
    int tg  = base + tok;
    float4 v = make_float4(0.f, 0.f, 0.f, 0.f);
    if (tg >= 0)
      v = *(const float4*)&kv[((size_t)(b*T_ + tg)*H_ + h)*128 + dq];
    float* dst = (dq < 64) ? (ks + dq*AT_PAD + tok) : (vs + (dq-64)*AT_PAD + tok);
    dst[0]        = v.x;
    dst[AT_PAD]   = v.y;
    dst[2*AT_PAD] = v.z;
    dst[3*AT_PAD] = v.w;
  }
  __syncthreads();

  const int tg = c * 128 + tid;
  const float* qp = &q[((size_t)(b*T_ + tg)*H_ + h)*HD_];
  float qr[64];
#pragma unroll
  for (int i = 0; i < 16; i++) {
    float4 f = *(const float4*)(qp + 4*i);
    qr[4*i]=f.x; qr[4*i+1]=f.y; qr[4*i+2]=f.z; qr[4*i+3]=f.w;
  }
  float acc[64];
#pragma unroll
  for (int d = 0; d < 64; d++) acc[d] = 0.f;

  const int jt = tid + W_;
  for (int w = 0; w < W_; w++) {
    int j = jt - 1 - w;
    float s = 0.f;
#pragma unroll
    for (int d = 0; d < 64; d++) s += qr[d] * ks[d*AT_PAD + j];
    float tau = 1.f / (1.f + expf(-s * 0.125f));
#pragma unroll
    for (int d = 0; d < 64; d++) acc[d] += tau * vs[d*AT_PAD + j];
  }
  float* mp = &msg[((size_t)(b*T_ + tg)*H_ + h)*HD_];
#pragma unroll
  for (int i = 0; i < 16; i++)
    *(float4*)(mp + 4*i) = make_float4(acc[4*i],acc[4*i+1],acc[4*i+2],acc[4*i+3]);
}

// ======================= LayerNorm variants =======================
template<int MODE>
__global__ __launch_bounds__(128) void ln_kernel(
    const float* __restrict__ x, const float* __restrict__ add,
    const float* __restrict__ g, const float* __restrict__ bb,
    const float* __restrict__ freqs, const float* __restrict__ phases,
    const float* __restrict__ amp, float* __restrict__ out) {
  const int row = blockIdx.x;
  const int i = threadIdx.x;
  float4 f = ((const float4*)(x + (size_t)row*D_))[i];
  if (MODE >= 1) {
    float4 a = ((const float4*)(add + (size_t)row*D_))[i];
    f.x+=a.x; f.y+=a.y; f.z+=a.z; f.w+=a.w;
  }
  float s  = f.x + f.y + f.z + f.w;
  float ss = f.x*f.x + f.y*f.y + f.z*f.z + f.w*f.w;
#pragma unroll
  for (int o = 16; o > 0; o >>= 1) {
    s  += __shfl_xor_sync(0xffffffffu, s,  o);
    ss += __shfl_xor_sync(0xffffffffu, ss, o);
  }
  __shared__ float rs[4], rss[4];
  if ((i & 31) == 0) { rs[i>>5] = s; rss[i>>5] = ss; }
  __syncthreads();
  s  = rs[0]  + rs[1]  + rs[2]  + rs[3];
  ss = rss[0] + rss[1] + rss[2] + rss[3];
  const float mu   = s * (1.f/D_);
  const float var  = ss * (1.f/D_) - mu*mu;
  const float rstd = rsqrtf(var + 1e-5f);
  float4 gv = ((const float4*)g)[i];
  float4 bv = ((const float4*)bb)[i];
  float4 o;
  o.x = (f.x-mu)*rstd*gv.x + bv.x;
  o.y = (f.y-mu)*rstd*gv.y + bv.y;
  o.z = (f.z-mu)*rstd*gv.z + bv.z;
  o.w = (f.w-mu)*rstd*gv.w + bv.w;
  if (MODE == 1) {
    float t  = (float)(row & (T_-1));
    float av = amp[0];
    float4 fr = ((const float4*)freqs)[i];
    float4 ph = ((const float4*)phases)[i];
    o.x *= 1.f + av*sinf(t*fr.x + ph.x);
    o.y *= 1.f + av*sinf(t*fr.y + ph.y);
    o.z *= 1.f + av*sinf(t*fr.z + ph.z);
    o.w *= 1.f + av*sinf(t*fr.w + ph.w);
  }
  ((float4*)(out + (size_t)row*D_))[i] = o;
}

// ======================= silu(gate) * val =======================
__global__ void silu_mul_kernel(const float* __restrict__ gg,
                                const float* __restrict__ vv,
                                float* __restrict__ out, int n4) {
  int i = blockIdx.x*blockDim.x + threadIdx.x;
  if (i >= n4) return;
  float4 gq = ((const float4*)gg)[i];
  float4 vq = ((const float4*)vv)[i];
  float4 o;
  o.x = gq.x / (1.f + expf(-gq.x)) * vq.x;
  o.y = gq.y / (1.f + expf(-gq.y)) * vq.y;
  o.z = gq.z / (1.f + expf(-gq.z)) * vq.z;
  o.w = gq.w / (1.f + expf(-gq.w)) * vq.w;
  ((float4*)out)[i] = o;
}

// ======================= launch =======================
static inline void run_gemm(const __nv_bfloat16* a2, const __nv_bfloat16* b2,
                            float* c, int N, int K3) {
  gemm_mma<<<dim3(N / 128, NTOK / 128), 256, GEMM_DYN_SMEM>>>(a2, b2, c, N, K3);
}

extern "C" void kernel_launch(void* const* d_in, const int* in_sizes, int n_in,
                              void* d_out, int out_size) {
  const float* x      = (const float*)d_in[0];
  const float* pre_g  = (const float*)d_in[1];
  const float* pre_b  = (const float*)d_in[2];
  const float* wq     = (const float*)d_in[3];
  const float* wkv    = (const float*)d_in[4];
  const float* wo     = (const float*)d_in[5];
  const float* attn_g = (const float*)d_in[6];
  const float* attn_b = (const float*)d_in[7];
  const float* freqs  = (const float*)d_in[8];
  const float* phases = (const float*)d_in[9];
  const float* amp    = (const float*)d_in[10];
  const float* w_gate = (const float*)d_in[11];
  const float* w_val  = (const float*)d_in[12];
  const float* w_proj = (const float*)d_in[13];
  const float* ffn_g  = (const float*)d_in[14];
  const float* ffn_b  = (const float*)d_in[15];

  float *h, *q, *kv, *msg, *tmp, *y, *gate, *val, *z;
  __nv_bfloat16 *a2, *b2;
  cudaGetSymbolAddress((void**)&h,    g_h);
  cudaGetSymbolAddress((void**)&q,    g_q);
  cudaGetSymbolAddress((void**)&kv,   g_kv);
  cudaGetSymbolAddress((void**)&msg,  g_msg);
  cudaGetSymbolAddress((void**)&tmp,  g_tmp);
  cudaGetSymbolAddress((void**)&y,    g_y);
  cudaGetSymbolAddress((void**)&gate, g_gate);
  cudaGetSymbolAddress((void**)&val,  g_val);
  cudaGetSymbolAddress((void**)&z,    g_z);
  cudaGetSymbolAddress((void**)&a2,   g_a2);
  cudaGetSymbolAddress((void**)&b2,   g_b2);

  const int ATTN_SMEM = 2 * 64 * AT_PAD * sizeof(float);
  cudaFuncSetAttribute(attn_kernel, cudaFuncAttributeMaxDynamicSharedMemorySize, ATTN_SMEM);
  cudaFuncSetAttribute(gemm_mma, cudaFuncAttributeMaxDynamicSharedMemorySize, GEMM_DYN_SMEM);

  // 1) h = LN(x)
  ln_kernel<0><<<NTOK, 128>>>(x, nullptr, pre_g, pre_b, nullptr, nullptr, nullptr, h);

  // 2) split h, then q = h@wq, kv = h@wkv (bf16x3 tensor-core GEMMs)
  split_a_kernel<<<(NTOK * (D_/4)) / 256, 256>>>(h, a2, D_);
  split_bt_kernel<<<dim3(D_/32, D_/32), dim3(32,32)>>>(wq, b2, D_, D_);
  run_gemm(a2, b2, q, D_, 3*D_);
  split_bt_kernel<<<dim3(2*D_/32, D_/32), dim3(32,32)>>>(wkv, b2, D_, 2*D_);
  run_gemm(a2, b2, kv, 2*D_, 3*D_);

  // 3) windowed sigmoid attention
  attn_kernel<<<dim3(T_/128, H_, B_), 128, ATTN_SMEM>>>(q, kv, msg);

  // 4) tmp = msg@wo ; y = LN(h+tmp) * (1 + amp*sin(...))
  split_a_kernel<<<(NTOK * (D_/4)) / 256, 256>>>(msg, a2, D_);
  split_bt_kernel<<<dim3(D_/32, D_/32), dim3(32,32)>>>(wo, b2, D_, D_);
  run_gemm(a2, b2, tmp, D_, 3*D_);
  ln_kernel<1><<<NTOK, 128>>>(h, tmp, attn_g, attn_b, freqs, phases, amp, y);

  // 5) FFN
  split_a_kernel<<<(NTOK * (D_/4)) / 256, 256>>>(y, a2, D_);
  split_bt_kernel<<<dim3(HID_/32, D_/32), dim3(32,32)>>>(w_gate, b2, D_, HID_);
  run_gemm(a2, b2, gate, HID_, 3*D_);
  split_bt_kernel<<<dim3(HID_/32, D_/32), dim3(32,32)>>>(w_val, b2, D_, HID_);
  run_gemm(a2, b2, val, HID_, 3*D_);
  {
    int n4 = NTOK * HID_ / 4;
    silu_mul_kernel<<<(n4 + 255)/256, 256>>>(gate, val, gate, n4);
  }
  split_a_kernel<<<(NTOK * (HID_/4)) / 256, 256>>>(gate, a2, HID_);
  split_bt_kernel<<<dim3(D_/32, HID_/32), dim3(32,32)>>>(w_proj, b2, HID_, D_);
  run_gemm(a2, b2, z, D_, 3*HID_);

  // 6) out = LN(y + z)
  ln_kernel<2><<<NTOK, 128>>>(y, z, ffn_g, ffn_b, nullptr, nullptr, nullptr, (float*)d_out);
}

// round 4
// speedup vs baseline: 2.5780x; 1.0636x over previous
#include <cuda_runtime.h>
#include <cuda_bf16.h>
#include <math.h>
#include <stdint.h>

#define B_   2
#define T_   4096
#define D_   512
#define H_   8
#define HD_  64
#define W_   32
#define HID_ 1536
#define NTOK (B_*T_)

// ---------------- scratch (device globals; no allocs allowed) ----------------
__device__ float g_h  [(size_t)NTOK * D_];
__device__ float g_qkv[(size_t)NTOK * 3 * D_];       // [q(512) | kv(1024)]
__device__ float g_tmp[(size_t)NTOK * D_];
__device__ float g_y  [(size_t)NTOK * D_];
__device__ float g_gv [(size_t)NTOK * 2 * HID_];     // [gate(1536) | val(1536)]
__device__ float g_z  [(size_t)NTOK * D_];
__device__ __nv_bfloat16 g_a2[(size_t)NTOK * 3 * HID_];   // split A, max K=1536
__device__ __nv_bfloat16 g_b2[(size_t)4718592];           // split B^T, max 3072 x 1536

// ======================= PTX helpers (baseline ISA only) =======================
__device__ __forceinline__ uint32_t s2u(const void* p) {
  uint32_t a;
  asm("{ .reg .u64 t; cvta.to.shared.u64 t, %1; cvt.u32.u64 %0, t; }" : "=r"(a) : "l"(p));
  return a;
}
__device__ __forceinline__ void cp16(uint32_t dst, const void* src) {
  asm volatile("cp.async.cg.shared.global [%0], [%1], 16;" :: "r"(dst), "l"(src) : "memory");
}
__device__ __forceinline__ void cp_commit() { asm volatile("cp.async.commit_group;" ::: "memory"); }
template<int N>
__device__ __forceinline__ void cp_wait() { asm volatile("cp.async.wait_group %0;" :: "n"(N) : "memory"); }

__device__ __forceinline__ void ldsm4(uint32_t* r, uint32_t addr) {
  asm volatile("ldmatrix.sync.aligned.m8n8.x4.shared.b16 {%0,%1,%2,%3}, [%4];"
               : "=r"(r[0]), "=r"(r[1]), "=r"(r[2]), "=r"(r[3]) : "r"(addr));
}
__device__ __forceinline__ void mma16816(float* d, const uint32_t* a, const uint32_t* b) {
  asm volatile(
      "mma.sync.aligned.m16n8k16.row.col.f32.bf16.bf16.f32 "
      "{%0,%1,%2,%3}, {%4,%5,%6,%7}, {%8,%9}, {%0,%1,%2,%3};"
      : "+f"(d[0]), "+f"(d[1]), "+f"(d[2]), "+f"(d[3])
      : "r"(a[0]), "r"(a[1]), "r"(a[2]), "r"(a[3]), "r"(b[0]), "r"(b[1]));
}

__device__ __forceinline__ void split4(const float4& v, uint2& H, uint2& L) {
  union { __nv_bfloat16 b[4]; uint2 u; } hu, lu;
  hu.b[0] = __float2bfloat16(v.x); hu.b[1] = __float2bfloat16(v.y);
  hu.b[2] = __float2bfloat16(v.z); hu.b[3] = __float2bfloat16(v.w);
  lu.b[0] = __float2bfloat16(v.x - __bfloat162float(hu.b[0]));
  lu.b[1] = __float2bfloat16(v.y - __bfloat162float(hu.b[1]));
  lu.b[2] = __float2bfloat16(v.z - __bfloat162float(hu.b[2]));
  lu.b[3] = __float2bfloat16(v.w - __bfloat162float(hu.b[3]));
  H = hu.u; L = lu.u;
}

// ======================= weight split: w[K,N] -> B2row[n, 3K] = [hi|hi|lo] ======
__global__ void split_bt_kernel(const float* __restrict__ w,
                                __nv_bfloat16* __restrict__ out, int K, int N) {
  __shared__ float t[32][33];
  int n0 = blockIdx.x * 32, k0 = blockIdx.y * 32;
  t[threadIdx.y][threadIdx.x] = w[(size_t)(k0 + threadIdx.y) * N + n0 + threadIdx.x];
  __syncthreads();
  int n = n0 + threadIdx.y, k = k0 + threadIdx.x;
  float x = t[threadIdx.x][threadIdx.y];
  __nv_bfloat16 hi = __float2bfloat16(x);
  __nv_bfloat16 lo = __float2bfloat16(x - __bfloat162float(hi));
  size_t base = (size_t)n * 3 * K;
  out[base + k]         = hi;
  out[base + K + k]     = hi;
  out[base + 2 * K + k] = lo;
}

// ======================= mma.sync bf16 GEMM =======================
// C[M,N] = A2[M,K3] @ B2[N,K3]^T. CTA tile 128x128, BK=64, 2-stage double buffer,
// ONE __syncthreads per iteration. 8 warps, warp tile 32m x 64n.
#define STAGE_BYTES 32768          /* A 16KB + B 16KB */
#define GEMM_DYN_SMEM (2*STAGE_BYTES + 1024)

__global__ __launch_bounds__(256, 2) void gemm_mma(
    const __nv_bfloat16* __restrict__ A2, const __nv_bfloat16* __restrict__ B2,
    float* __restrict__ C, int N, int K3) {
  extern __shared__ char smraw[];
  uint32_t sb0 = s2u(smraw);
  const uint32_t sb = sb0 + ((1024u - (sb0 & 1023u)) & 1023u);

  const int tid = threadIdx.x, lane = tid & 31, wid = tid >> 5;
  const int bm = blockIdx.y * 128, bn = blockIdx.x * 128;
  const int wm = (wid >> 1) * 32, wn = (wid & 1) * 64;

  uint32_t aOff[4], bOff[4];
  const char *aSrc[4], *bSrc[4];
#pragma unroll
  for (int j = 0; j < 4; j++) {
    int s = tid + j * 256, r = s >> 3, c = s & 7;
    uint32_t off = (uint32_t)(r * 128 + ((c ^ (r & 7)) << 4));
    aOff[j] = off;
    bOff[j] = off;
    aSrc[j] = (const char*)(A2 + (size_t)(bm + r) * K3) + c * 16;
    bSrc[j] = (const char*)(B2 + (size_t)(bn + r) * K3) + c * 16;
  }

  float acc[2][8][4];
#pragma unroll
  for (int mt = 0; mt < 2; mt++)
#pragma unroll
    for (int nt = 0; nt < 8; nt++)
#pragma unroll
      for (int e = 0; e < 4; e++) acc[mt][nt][e] = 0.f;

  const int arow = wm + (lane & 15);
  const int ach  = lane >> 4;
  const int brow = wn + (lane & 7) + ((lane >> 1) & 8);
  const int bch  = (lane >> 3) & 1;

  const int nIter = K3 >> 6;

  auto loadStage = [&](int i) {
    uint32_t st = sb + (uint32_t)(i & 1) * STAGE_BYTES;
    size_t koff = (size_t)i * 128;
#pragma unroll
    for (int j = 0; j < 4; j++) cp16(st + aOff[j], aSrc[j] + koff);
#pragma unroll
    for (int j = 0; j < 4; j++) cp16(st + 16384 + bOff[j], bSrc[j] + koff);
    cp_commit();
  };

  loadStage(0);

  for (int i = 0; i < nIter; i++) {
    cp_wait<0>();           // my stage-i data landed (only group pending)
    __syncthreads();        // publish to CTA + retire iter i-1 reads
    if (i + 1 < nIter) loadStage(i + 1);   // safe: (i+1)&1 buffer retired above

    const uint32_t sa  = sb + (uint32_t)(i & 1) * STAGE_BYTES;
    const uint32_t sbB = sa + 16384;
#pragma unroll
    for (int ks = 0; ks < 4; ks++) {
      uint32_t afr[2][4];
#pragma unroll
      for (int mt = 0; mt < 2; mt++) {
        int row = arow + mt * 16;
        int ch  = 2 * ks + ach;
        ldsm4(afr[mt], sa + row * 128 + (((uint32_t)(ch ^ (row & 7))) << 4));
      }
      uint32_t bfr[4][4];
#pragma unroll
      for (int nt = 0; nt < 4; nt++) {
        int row = brow + nt * 16;
        int ch  = 2 * ks + bch;
        ldsm4(bfr[nt], sbB + row * 128 + (((uint32_t)(ch ^ (row & 7))) << 4));
      }
#pragma unroll
      for (int mt = 0; mt < 2; mt++)
#pragma unroll
        for (int n8 = 0; n8 < 8; n8++)
          mma16816(acc[mt][n8], afr[mt], &bfr[n8 >> 1][(n8 & 1) * 2]);
    }
  }

  const int crow = lane >> 2;
  const int ccol = (lane & 3) * 2;
#pragma unroll
  for (int mt = 0; mt < 2; mt++) {
#pragma unroll
    for (int n8 = 0; n8 < 8; n8++) {
      size_t r0 = (size_t)(bm + wm + mt * 16 + crow) * N + (bn + wn + n8 * 8 + ccol);
      *(float2*)&C[r0]                 = make_float2(acc[mt][n8][0], acc[mt][n8][1]);
      *(float2*)&C[r0 + (size_t)8 * N] = make_float2(acc[mt][n8][2], acc[mt][n8][3]);
    }
  }
}

// ======================= windowed sigmoid attention =======================
// reads q/kv from combined qkv buffer [tok][1536]; writes SPLIT output into a2
// (K=512 layout: [hi | lo | hi]).
#define AT_TOKS (128 + W_)
#define AT_PAD  161

__global__ __launch_bounds__(128) void attn_kernel(
    const float* __restrict__ qkv, __nv_bfloat16* __restrict__ a2) {
  extern __shared__ float smf[];
  float* ks = smf;
  float* vs = smf + 64 * AT_PAD;
  const int c = blockIdx.x, h = blockIdx.y, b = blockIdx.z;
  const int base = c * 128 - W_;
  const int tid = threadIdx.x;

  for (int i4 = tid; i4 < AT_TOKS * 32; i4 += 128) {
    int tok = i4 >> 5;
    int dq  = (i4 & 31) << 2;
    int tg  = base + tok;
    float4 v = make_float4(0.f, 0.f, 0.f, 0.f);
    if (tg >= 0)
      v = *(const float4*)&qkv[(size_t)(b*T_ + tg)*(3*D_) + D_ + h*128 + dq];
    float* dst = (dq < 64) ? (ks + dq*AT_PAD + tok) : (vs + (dq-64)*AT_PAD + tok);
    dst[0]        = v.x;
    dst[AT_PAD]   = v.y;
    dst[2*AT_PAD] = v.z;
    dst[3*AT_PAD] = v.w;
  }
  __syncthreads();

  const int tg = c * 128 + tid;
  const float* qp = &qkv[(size_t)(b*T_ + tg)*(3*D_) + h*HD_];
  float qr[64];
#pragma unroll
  for (int i = 0; i < 16; i++) {
    float4 f = *(const float4*)(qp + 4*i);
    qr[4*i]=f.x; qr[4*i+1]=f.y; qr[4*i+2]=f.z; qr[4*i+3]=f.w;
  }
  float acc[64];
#pragma unroll
  for (int d = 0; d < 64; d++) acc[d] = 0.f;

  const int jt = tid + W_;
  for (int w = 0; w < W_; w++) {
    int j = jt - 1 - w;
    float s = 0.f;
#pragma unroll
    for (int d = 0; d < 64; d++) s += qr[d] * ks[d*AT_PAD + j];
    float tau = 1.f / (1.f + expf(-s * 0.125f));
#pragma unroll
    for (int d = 0; d < 64; d++) acc[d] += tau * vs[d*AT_PAD + j];
  }
  // split epilogue into a2[tok][3*512]
  size_t abase = (size_t)(b*T_ + tg) * (3 * D_);
  int off = h * HD_;
#pragma unroll
  for (int i = 0; i < 16; i++) {
    float4 v = make_float4(acc[4*i], acc[4*i+1], acc[4*i+2], acc[4*i+3]);
    uint2 Hu, Lu; split4(v, Hu, Lu);
    *(uint2*)(a2 + abase + off + 4*i)            = Hu;
    *(uint2*)(a2 + abase + D_ + off + 4*i)       = Lu;
    *(uint2*)(a2 + abase + 2*D_ + off + 4*i)     = Hu;
  }
}

// ======================= LayerNorm (+residual, +mod, +split out) =======================
// MODE 0: out = LN(x);             MODE 1: out = LN(x+add) * (1+amp*sin(...));
// MODE 2: out = LN(x+add)
// SPLIT: also write [hi|lo|hi] bf16 rows (K=512) into a2.
template<int MODE, int SPLIT>
__global__ __launch_bounds__(128) void ln_kernel(
    const float* __restrict__ x, const float* __restrict__ add,
    const float* __restrict__ g, const float* __restrict__ bb,
    const float* __restrict__ freqs, const float* __restrict__ phases,
    const float* __restrict__ amp, float* __restrict__ out,
    __nv_bfloat16* __restrict__ a2) {
  const int row = blockIdx.x;
  const int i = threadIdx.x;
  float4 f = ((const float4*)(x + (size_t)row*D_))[i];
  if (MODE >= 1) {
    float4 a = ((const float4*)(add + (size_t)row*D_))[i];
    f.x+=a.x; f.y+=a.y; f.z+=a.z; f.w+=a.w;
  }
  float s  = f.x + f.y + f.z + f.w;
  float ss = f.x*f.x + f.y*f.y + f.z*f.z + f.w*f.w;
#pragma unroll
  for (int o = 16; o > 0; o >>= 1) {
    s  += __shfl_xor_sync(0xffffffffu, s,  o);
    ss += __shfl_xor_sync(0xffffffffu, ss, o);
  }
  __shared__ float rs[4], rss[4];
  if ((i & 31) == 0) { rs[i>>5] = s; rss[i>>5] = ss; }
  __syncthreads();
  s  = rs[0]  + rs[1]  + rs[2]  + rs[3];
  ss = rss[0] + rss[1] + rss[2] + rss[3];
  const float mu   = s * (1.f/D_);
  const float var  = ss * (1.f/D_) - mu*mu;
  const float rstd = rsqrtf(var + 1e-5f);
  float4 gv = ((const float4*)g)[i];
  float4 bv = ((const float4*)bb)[i];
  float4 o;
  o.x = (f.x-mu)*rstd*gv.x + bv.x;
  o.y = (f.y-mu)*rstd*gv.y + bv.y;
  o.z = (f.z-mu)*rstd*gv.z + bv.z;
  o.w = (f.w-mu)*rstd*gv.w + bv.w;
  if (MODE == 1) {
    float t  = (float)(row & (T_-1));
    float av = amp[0];
    float4 fr = ((const float4*)freqs)[i];
    float4 ph = ((const float4*)phases)[i];
    o.x *= 1.f + av*sinf(t*fr.x + ph.x);
    o.y *= 1.f + av*sinf(t*fr.y + ph.y);
    o.z *= 1.f + av*sinf(t*fr.z + ph.z);
    o.w *= 1.f + av*sinf(t*fr.w + ph.w);
  }
  ((float4*)(out + (size_t)row*D_))[i] = o;
  if (SPLIT) {
    uint2 Hu, Lu; split4(o, Hu, Lu);
    size_t base = (size_t)row * 3 * D_;
    int k = i * 4;
    *(uint2*)(a2 + base + k)          = Hu;
    *(uint2*)(a2 + base + D_ + k)     = Lu;
    *(uint2*)(a2 + base + 2*D_ + k)   = Hu;
  }
}

// ======================= silu(gate)*val -> split a2 (K=1536) =======================
__global__ __launch_bounds__(256) void silu_mul_split_kernel(
    const float* __restrict__ gv, __nv_bfloat16* __restrict__ a2) {
  int idx = blockIdx.x * 256 + threadIdx.x;     // over NTOK * HID/4
  int kq = HID_ >> 2;                           // 384
  int m = idx / kq;
  int k = (idx - m * kq) << 2;
  const float* rowp = gv + (size_t)m * (2 * HID_);
  float4 gq = *(const float4*)(rowp + k);
  float4 vq = *(const float4*)(rowp + HID_ + k);
  float4 o;
  o.x = gq.x / (1.f + expf(-gq.x)) * vq.x;
  o.y = gq.y / (1.f + expf(-gq.y)) * vq.y;
  o.z = gq.z / (1.f + expf(-gq.z)) * vq.z;
  o.w = gq.w / (1.f + expf(-gq.w)) * vq.w;
  uint2 Hu, Lu; split4(o, Hu, Lu);
  size_t base = (size_t)m * 3 * HID_;
  *(uint2*)(a2 + base + k)            = Hu;
  *(uint2*)(a2 + base + HID_ + k)     = Lu;
  *(uint2*)(a2 + base + 2*HID_ + k)   = Hu;
}

// ======================= launch =======================
static inline void run_gemm(const __nv_bfloat16* a2, const __nv_bfloat16* b2,
                            float* c, int N, int K3) {
  gemm_mma<<<dim3(N / 128, NTOK / 128), 256, GEMM_DYN_SMEM>>>(a2, b2, c, N, K3);
}

extern "C" void kernel_launch(void* const* d_in, const int* in_sizes, int n_in,
                              void* d_out, int out_size) {
  const float* x      = (const float*)d_in[0];
  const float* pre_g  = (const float*)d_in[1];
  const float* pre_b  = (const float*)d_in[2];
  const float* wq     = (const float*)d_in[3];
  const float* wkv    = (const float*)d_in[4];
  const float* wo     = (const float*)d_in[5];
  const float* attn_g = (const float*)d_in[6];
  const float* attn_b = (const float*)d_in[7];
  const float* freqs  = (const float*)d_in[8];
  const float* phases = (const float*)d_in[9];
  const float* amp    = (const float*)d_in[10];
  const float* w_gate = (const float*)d_in[11];
  const float* w_val  = (const float*)d_in[12];
  const float* w_proj = (const float*)d_in[13];
  const float* ffn_g  = (const float*)d_in[14];
  const float* ffn_b  = (const float*)d_in[15];

  float *h, *qkv, *tmp, *y, *gv, *z;
  __nv_bfloat16 *a2, *b2;
  cudaGetSymbolAddress((void**)&h,   g_h);
  cudaGetSymbolAddress((void**)&qkv, g_qkv);
  cudaGetSymbolAddress((void**)&tmp, g_tmp);
  cudaGetSymbolAddress((void**)&y,   g_y);
  cudaGetSymbolAddress((void**)&gv,  g_gv);
  cudaGetSymbolAddress((void**)&z,   g_z);
  cudaGetSymbolAddress((void**)&a2,  g_a2);
  cudaGetSymbolAddress((void**)&b2,  g_b2);

  const int ATTN_SMEM = 2 * 64 * AT_PAD * sizeof(float);
  cudaFuncSetAttribute(attn_kernel, cudaFuncAttributeMaxDynamicSharedMemorySize, ATTN_SMEM);
  cudaFuncSetAttribute(gemm_mma, cudaFuncAttributeMaxDynamicSharedMemorySize, GEMM_DYN_SMEM);

  // 1) h = LN(x) (+ split into a2, K=512)
  ln_kernel<0,1><<<NTOK, 128>>>(x, nullptr, pre_g, pre_b, nullptr, nullptr, nullptr, h, a2);

  // 2) qkv = h @ [wq | wkv] in one N=1536 GEMM
  split_bt_kernel<<<dim3(D_/32,   D_/32), dim3(32,32)>>>(wq,  b2,                              D_, D_);
  split_bt_kernel<<<dim3(2*D_/32, D_/32), dim3(32,32)>>>(wkv, b2 + (size_t)D_ * 3 * D_,        D_, 2*D_);
  run_gemm(a2, b2, qkv, 3*D_, 3*D_);

  // 3) attention -> split msg directly into a2 (K=512)
  attn_kernel<<<dim3(T_/128, H_, B_), 128, ATTN_SMEM>>>(qkv, a2);

  // 4) tmp = msg@wo ; y = LN(h+tmp)*(1+amp*sin) (+ split into a2)
  split_bt_kernel<<<dim3(D_/32, D_/32), dim3(32,32)>>>(wo, b2, D_, D_);
  run_gemm(a2, b2, tmp, D_, 3*D_);
  ln_kernel<1,1><<<NTOK, 128>>>(h, tmp, attn_g, attn_b, freqs, phases, amp, y, a2);

  // 5) FFN: gv = y @ [w_gate | w_val] in one N=3072 GEMM
  split_bt_kernel<<<dim3(HID_/32, D_/32), dim3(32,32)>>>(w_gate, b2,                           D_, HID_);
  split_bt_kernel<<<dim3(HID_/32, D_/32), dim3(32,32)>>>(w_val,  b2 + (size_t)HID_ * 3 * D_,   D_, HID_);
  run_gemm(a2, b2, gv, 2*HID_, 3*D_);
  // silu(gate)*val -> split into a2 (K=1536)
  silu_mul_split_kernel<<<(NTOK * (HID_/4)) / 256, 256>>>(gv, a2);
  // z = a @ w_proj
  split_bt_kernel<<<dim3(D_/32, HID_/32), dim3(32,32)>>>(w_proj, b2, HID_, D_);
  run_gemm(a2, b2, z, D_, 3*HID_);

  // 6) out = LN(y + z)
  ln_kernel<2,0><<<NTOK, 128>>>(y, z, ffn_g, ffn_b, nullptr, nullptr, nullptr, (float*)d_out, nullptr);
}